// round 1
// baseline (speedup 1.0000x reference)
#include <cuda_runtime.h>
#include <cuda_bf16.h>

// Problem constants
#define BATCH 32
#define TIME 1024
#define IN_DIM 512
#define HIDDEN 512

#define M_TOTAL (BATCH * TIME)   // 32768
#define N_TOTAL HIDDEN           // 512
#define K_TOTAL IN_DIM           // 512

// LIF constants (fp32 of exp(-dt/tau))
#define ALPHA_MEM 0.95122942450071400909f  // exp(-0.05)
#define ALPHA_SYN 0.81873075307798185867f  // exp(-0.2)
#define THRESHOLD 1.0f

// Scratch for I_in = spikes @ W + b : [B*T, H] = 64 MB
__device__ float g_Iin[(size_t)M_TOTAL * N_TOTAL];

// ---------------------------------------------------------------------------
// Kernel 1: fp32 GEMM  C[M,N] = A[M,K] * W[K,N] + bias[N]
// 128x128 block tile, BK=16, 256 threads, 8x8 per-thread micro-tile.
// ---------------------------------------------------------------------------
#define BM 128
#define BN 128
#define BK 16
#define TM 8
#define TN 8
#define PAD 4  // row padding (floats) to break store bank conflicts

__global__ __launch_bounds__(256)
void gemm_f32_kernel(const float* __restrict__ A,
                     const float* __restrict__ W,
                     const float* __restrict__ bias,
                     float* __restrict__ C)
{
    __shared__ float As[BK][BM + PAD];  // A transposed: As[k][m]
    __shared__ float Bs[BK][BN + PAD];

    const int bm = blockIdx.y * BM;
    const int bn = blockIdx.x * BN;
    const int tid = threadIdx.x;           // 0..255
    const int tx = tid & 15;               // 0..15 -> n micro-tile
    const int ty = tid >> 4;               // 0..15 -> m micro-tile

    // A-load mapping: 128 rows x 16 cols, float4 per thread, 2 passes
    const int arow = tid >> 2;             // 0..63
    const int acol = (tid & 3) << 2;       // 0,4,8,12
    // B-load mapping: 16 rows x 128 cols, float4 per thread, 2 passes
    const int brow = tid >> 5;             // 0..7
    const int bcol = (tid & 31) << 2;      // 0..124

    float acc[TM][TN];
#pragma unroll
    for (int i = 0; i < TM; i++)
#pragma unroll
        for (int j = 0; j < TN; j++)
            acc[i][j] = 0.0f;

    const float* Aptr = A + (size_t)bm * K_TOTAL;
    const float* Wptr = W + bn;

    for (int k0 = 0; k0 < K_TOTAL; k0 += BK) {
        // Load A tile (transposed into As)
#pragma unroll
        for (int r = 0; r < 2; r++) {
            float4 v = *(const float4*)(Aptr + (size_t)(arow + r * 64) * K_TOTAL + k0 + acol);
            As[acol + 0][arow + r * 64] = v.x;
            As[acol + 1][arow + r * 64] = v.y;
            As[acol + 2][arow + r * 64] = v.z;
            As[acol + 3][arow + r * 64] = v.w;
        }
        // Load B tile
#pragma unroll
        for (int r = 0; r < 2; r++) {
            float4 v = *(const float4*)(Wptr + (size_t)(k0 + brow + r * 8) * N_TOTAL + bcol);
            *(float4*)(&Bs[brow + r * 8][bcol]) = v;
        }
        __syncthreads();

#pragma unroll
        for (int k = 0; k < BK; k++) {
            float a[TM], bb[TN];
            float4 a0 = *(const float4*)(&As[k][ty * TM]);
            float4 a1 = *(const float4*)(&As[k][ty * TM + 4]);
            a[0] = a0.x; a[1] = a0.y; a[2] = a0.z; a[3] = a0.w;
            a[4] = a1.x; a[5] = a1.y; a[6] = a1.z; a[7] = a1.w;
            float4 b0 = *(const float4*)(&Bs[k][tx * TN]);
            float4 b1 = *(const float4*)(&Bs[k][tx * TN + 4]);
            bb[0] = b0.x; bb[1] = b0.y; bb[2] = b0.z; bb[3] = b0.w;
            bb[4] = b1.x; bb[5] = b1.y; bb[6] = b1.z; bb[7] = b1.w;
#pragma unroll
            for (int i = 0; i < TM; i++)
#pragma unroll
                for (int j = 0; j < TN; j++)
                    acc[i][j] = fmaf(a[i], bb[j], acc[i][j]);
        }
        __syncthreads();
    }

    // Epilogue: add bias, store with float4
    float4 bv0 = *(const float4*)(bias + bn + tx * TN);
    float4 bv1 = *(const float4*)(bias + bn + tx * TN + 4);
#pragma unroll
    for (int i = 0; i < TM; i++) {
        float* crow = C + (size_t)(bm + ty * TM + i) * N_TOTAL + bn + tx * TN;
        float4 o0, o1;
        o0.x = acc[i][0] + bv0.x; o0.y = acc[i][1] + bv0.y;
        o0.z = acc[i][2] + bv0.z; o0.w = acc[i][3] + bv0.w;
        o1.x = acc[i][4] + bv1.x; o1.y = acc[i][5] + bv1.y;
        o1.z = acc[i][6] + bv1.z; o1.w = acc[i][7] + bv1.w;
        *(float4*)(crow) = o0;
        *(float4*)(crow + 4) = o1;
    }
}

// ---------------------------------------------------------------------------
// Kernel 2: LIF scan. One thread per (b,h) neuron, serial over T.
//   i_syn = a_syn*i_syn + I_in[t]
//   v     = a_mem*v + i_syn
//   out   = (v > 1) ; v -= out
// Consecutive threads -> consecutive h -> coalesced per time step.
// ---------------------------------------------------------------------------
__global__ __launch_bounds__(256)
void lif_scan_kernel(const float* __restrict__ Iin,
                     float* __restrict__ out)
{
    const int g = blockIdx.x * blockDim.x + threadIdx.x;  // 0 .. B*H-1
    if (g >= BATCH * HIDDEN) return;
    const int b = g / HIDDEN;
    const int h = g - b * HIDDEN;

    const float* p = Iin + (size_t)b * TIME * HIDDEN + h;
    float* q = out + (size_t)b * TIME * HIDDEN + h;

    float v = 0.0f, s = 0.0f;
#pragma unroll 8
    for (int t = 0; t < TIME; t++) {
        float it = p[(size_t)t * HIDDEN];
        s = fmaf(ALPHA_SYN, s, it);
        v = fmaf(ALPHA_MEM, v, s);
        float o = (v > THRESHOLD) ? 1.0f : 0.0f;
        v -= o;
        q[(size_t)t * HIDDEN] = o;
    }
}

// ---------------------------------------------------------------------------
extern "C" void kernel_launch(void* const* d_in, const int* in_sizes, int n_in,
                              void* d_out, int out_size)
{
    const float* spikes = (const float*)d_in[0];  // [B, T, I]
    const float* W      = (const float*)d_in[1];  // [I, H]
    const float* bias   = (const float*)d_in[2];  // [H]
    float* out          = (float*)d_out;          // [B, T, H]

    float* Iin;
    cudaGetSymbolAddress((void**)&Iin, g_Iin);

    dim3 ggrid(N_TOTAL / BN, M_TOTAL / BM);  // (4, 256)
    gemm_f32_kernel<<<ggrid, 256>>>(spikes, W, bias, Iin);

    int nthreads = BATCH * HIDDEN;           // 16384
    lif_scan_kernel<<<nthreads / 256, 256>>>(Iin, out);
}

// round 2
// speedup vs baseline: 1.1222x; 1.1222x over previous
#include <cuda_runtime.h>
#include <cuda_bf16.h>

// Problem constants
#define BATCH 32
#define TIME 1024
#define IN_DIM 512
#define HIDDEN 512

#define M_TOTAL (BATCH * TIME)   // 32768
#define N_TOTAL HIDDEN           // 512
#define K_TOTAL IN_DIM           // 512

// LIF constants
#define ALPHA_MEM 0.95122942450071400909f  // exp(-0.05)
#define ALPHA_SYN 0.81873075307798185867f  // exp(-0.2)
#define THRESHOLD 1.0f

// Scratch for I_in = spikes @ W + b : [B*T, H] = 64 MB
__device__ float g_Iin[(size_t)M_TOTAL * N_TOTAL];

typedef unsigned long long u64;

__device__ __forceinline__ u64 pack2(float x) {
    u64 r; unsigned xi = __float_as_uint(x);
    asm("mov.b64 %0, {%1, %1};" : "=l"(r) : "r"(xi));
    return r;
}
__device__ __forceinline__ void fma2(u64& d, u64 a, u64 b) {
    asm("fma.rn.f32x2 %0, %1, %2, %3;" : "=l"(d) : "l"(a), "l"(b), "l"(d));
}
__device__ __forceinline__ u64 add2(u64 a, u64 b) {
    u64 r;
    asm("add.rn.f32x2 %0, %1, %2;" : "=l"(r) : "l"(a), "l"(b));
    return r;
}

// ---------------------------------------------------------------------------
// Kernel 1: fp32 GEMM via packed FFMA2 (fma.rn.f32x2).
// C[M,N] = A[M,K] * W[K,N] + bias[N]
// 128x128 block tile, BK=16, 256 threads, 8x8 per-thread micro-tile
// computed as 8 x (4 packed pairs).
// ---------------------------------------------------------------------------
#define BM 128
#define BN 128
#define BK 16
#define TM 8
#define TN 8
#define PAD 4  // row padding (floats); row pitch 132*4=528B stays 16B-aligned

__global__ __launch_bounds__(256)
void gemm_f32_kernel(const float* __restrict__ A,
                     const float* __restrict__ W,
                     const float* __restrict__ bias,
                     float* __restrict__ C)
{
    __shared__ float As[BK][BM + PAD];  // A transposed: As[k][m]
    __shared__ float Bs[BK][BN + PAD];

    const int bm = blockIdx.y * BM;
    const int bn = blockIdx.x * BN;
    const int tid = threadIdx.x;           // 0..255
    const int tx = tid & 15;               // n micro-tile
    const int ty = tid >> 4;               // m micro-tile

    const int arow = tid >> 2;             // 0..63
    const int acol = (tid & 3) << 2;       // 0,4,8,12
    const int brow = tid >> 5;             // 0..7
    const int bcol = (tid & 31) << 2;      // 0..124

    u64 acc[TM][TN / 2];
#pragma unroll
    for (int i = 0; i < TM; i++)
#pragma unroll
        for (int j = 0; j < TN / 2; j++)
            acc[i][j] = 0ULL;

    const float* Aptr = A + (size_t)bm * K_TOTAL;
    const float* Wptr = W + bn;

    for (int k0 = 0; k0 < K_TOTAL; k0 += BK) {
        // Load A tile (transposed into As)
#pragma unroll
        for (int r = 0; r < 2; r++) {
            float4 v = *(const float4*)(Aptr + (size_t)(arow + r * 64) * K_TOTAL + k0 + acol);
            As[acol + 0][arow + r * 64] = v.x;
            As[acol + 1][arow + r * 64] = v.y;
            As[acol + 2][arow + r * 64] = v.z;
            As[acol + 3][arow + r * 64] = v.w;
        }
        // Load B tile
#pragma unroll
        for (int r = 0; r < 2; r++) {
            float4 v = *(const float4*)(Wptr + (size_t)(k0 + brow + r * 8) * N_TOTAL + bcol);
            *(float4*)(&Bs[brow + r * 8][bcol]) = v;
        }
        __syncthreads();

#pragma unroll
        for (int k = 0; k < BK; k++) {
            // a: 8 scalars, broadcast-packed
            float4 a0 = *(const float4*)(&As[k][ty * TM]);
            float4 a1 = *(const float4*)(&As[k][ty * TM + 4]);
            u64 ap[TM];
            ap[0] = pack2(a0.x); ap[1] = pack2(a0.y);
            ap[2] = pack2(a0.z); ap[3] = pack2(a0.w);
            ap[4] = pack2(a1.x); ap[5] = pack2(a1.y);
            ap[6] = pack2(a1.z); ap[7] = pack2(a1.w);
            // b: 8 scalars = 4 packed pairs (two 16B loads)
            ulonglong2 bq0 = *(const ulonglong2*)(&Bs[k][tx * TN]);
            ulonglong2 bq1 = *(const ulonglong2*)(&Bs[k][tx * TN + 4]);
            u64 bp0 = bq0.x, bp1 = bq0.y, bp2 = bq1.x, bp3 = bq1.y;
#pragma unroll
            for (int i = 0; i < TM; i++) {
                fma2(acc[i][0], ap[i], bp0);
                fma2(acc[i][1], ap[i], bp1);
                fma2(acc[i][2], ap[i], bp2);
                fma2(acc[i][3], ap[i], bp3);
            }
        }
        __syncthreads();
    }

    // Epilogue: packed bias add, 16B stores
    ulonglong2 bv0 = *(const ulonglong2*)(bias + bn + tx * TN);
    ulonglong2 bv1 = *(const ulonglong2*)(bias + bn + tx * TN + 4);
#pragma unroll
    for (int i = 0; i < TM; i++) {
        float* crow = C + (size_t)(bm + ty * TM + i) * N_TOTAL + bn + tx * TN;
        ulonglong2 o0, o1;
        o0.x = add2(acc[i][0], bv0.x);
        o0.y = add2(acc[i][1], bv0.y);
        o1.x = add2(acc[i][2], bv1.x);
        o1.y = add2(acc[i][3], bv1.y);
        *(ulonglong2*)(crow) = o0;
        *(ulonglong2*)(crow + 4) = o1;
    }
}

// ---------------------------------------------------------------------------
// Kernel 2: LIF scan. One thread per (b,h) neuron, serial over T.
// 64-thread blocks -> 256 blocks -> all 148 SMs busy.
// Register double-buffering (U=16) for MLP=16 DRAM prefetch.
// ---------------------------------------------------------------------------
#define U 16

__global__ __launch_bounds__(64)
void lif_scan_kernel(const float* __restrict__ Iin,
                     float* __restrict__ out)
{
    const int g = blockIdx.x * 64 + threadIdx.x;  // 0 .. B*H-1
    const int b = g >> 9;          // / HIDDEN
    const int h = g & (HIDDEN - 1);

    const float* p = Iin + (size_t)b * TIME * HIDDEN + h;
    float* q = out + (size_t)b * TIME * HIDDEN + h;

    float cur[U], nxt[U];
#pragma unroll
    for (int i = 0; i < U; i++)
        cur[i] = __ldcs(p + (size_t)i * HIDDEN);

    float v = 0.0f, s = 0.0f;
    for (int t0 = 0; t0 < TIME; t0 += U) {
        const int tn = t0 + U;
        if (tn < TIME) {
#pragma unroll
            for (int i = 0; i < U; i++)
                nxt[i] = __ldcs(p + (size_t)(tn + i) * HIDDEN);
        }
#pragma unroll
        for (int i = 0; i < U; i++) {
            s = fmaf(ALPHA_SYN, s, cur[i]);
            v = fmaf(ALPHA_MEM, v, s);
            float o = (v > THRESHOLD) ? 1.0f : 0.0f;
            v -= o;
            __stcs(q + (size_t)(t0 + i) * HIDDEN, o);
        }
#pragma unroll
        for (int i = 0; i < U; i++) cur[i] = nxt[i];
    }
}

// ---------------------------------------------------------------------------
extern "C" void kernel_launch(void* const* d_in, const int* in_sizes, int n_in,
                              void* d_out, int out_size)
{
    const float* spikes = (const float*)d_in[0];  // [B, T, I]
    const float* W      = (const float*)d_in[1];  // [I, H]
    const float* bias   = (const float*)d_in[2];  // [H]
    float* out          = (float*)d_out;          // [B, T, H]

    float* Iin;
    cudaGetSymbolAddress((void**)&Iin, g_Iin);

    dim3 ggrid(N_TOTAL / BN, M_TOTAL / BM);  // (4, 256)
    gemm_f32_kernel<<<ggrid, 256>>>(spikes, W, bias, Iin);

    lif_scan_kernel<<<(BATCH * HIDDEN) / 64, 64>>>(Iin, out);
}